// round 6
// baseline (speedup 1.0000x reference)
#include <cuda_runtime.h>
#include <cstdint>

#define NB      8
#define NPER    4096
#define NTOT    32768
#define KNN     16
#define DIN     32
#define DH      64
#define DOUT    128

// ---------------- device scratch ----------------
static __device__ int   g_nbr[NTOT * KNN];
static __device__ float g_xw [NTOT * DH];
static __device__ float g_agg[NTOT * DH];

// ---------------- exact-arithmetic helpers (match XLA fp32) ----------------
__device__ __forceinline__ float sq3_exact(float x, float y, float z) {
    // jnp.sum(pos*pos, -1): mul, mul, mul then left-to-right adds, per-op rounding
    return __fadd_rn(__fadd_rn(__fmul_rn(x, x), __fmul_rn(y, y)), __fmul_rn(z, z));
}
__device__ __forceinline__ float dist_exact(float qx, float qy, float qz, float qsq,
                                            float cx, float cy, float cz, float csq) {
    // einsum dot: sequential-k fma chain (Eigen/cublas style)
    float dot = __fmaf_rn(qz, cz, __fmaf_rn(qy, cy, __fmul_rn(qx, cx)));
    // dist = (sq_n + sq_m) - 2*dot, elementwise rounding
    return __fsub_rn(__fadd_rn(qsq, csq), __fmul_rn(2.0f, dot));
}

// sorted ascending top-16 insert; strict-less + ascending candidate order
// == jax.lax.top_k lowest-index-wins tie-breaking.
__device__ __forceinline__ void insert16(float d, int gi, float (&bd)[16], int (&bi)[16]) {
    float cd = d; int ci = gi;
#pragma unroll
    for (int s = 0; s < 16; ++s) {
        bool p = cd < bd[s];
        float nd = p ? cd : bd[s]; float od = p ? bd[s] : cd;
        int   ni = p ? ci : bi[s]; int   oi = p ? bi[s] : ci;
        bd[s] = nd; bi[s] = ni; cd = od; ci = oi;
    }
}

// ---------------- K1: per-graph brute-force KNN ----------------
// grid = 128 (16 blocks/graph), 256 thr; thread = one query.
__global__ void __launch_bounds__(256) knn_kernel(const float* __restrict__ pos) {
    __shared__ float4 sc[2048];   // (x, y, z, sq)
    int graph = blockIdx.x >> 4;
    int q     = graph * NPER + (blockIdx.x & 15) * 256 + threadIdx.x;

    float qx = pos[q * 3 + 0], qy = pos[q * 3 + 1], qz = pos[q * 3 + 2];
    float qsq = sq3_exact(qx, qy, qz);

    float bd[16]; int bi[16];
#pragma unroll
    for (int s = 0; s < 16; ++s) { bd[s] = __int_as_float(0x7f800000); bi[s] = 0; }

    int cbase = graph * NPER;
#pragma unroll 1
    for (int chunk = 0; chunk < 2; ++chunk) {
#pragma unroll
        for (int u = 0; u < 8; ++u) {
            int li = threadIdx.x + u * 256;
            int gi = cbase + chunk * 2048 + li;
            float x = pos[gi * 3 + 0], y = pos[gi * 3 + 1], z = pos[gi * 3 + 2];
            sc[li] = make_float4(x, y, z, sq3_exact(x, y, z));
        }
        __syncthreads();
        int gbase = cbase + chunk * 2048;
#pragma unroll 1
        for (int j = 0; j < 2048; j += 4) {
            float4 c0 = sc[j], c1 = sc[j + 1], c2 = sc[j + 2], c3 = sc[j + 3];
            float d0 = dist_exact(qx, qy, qz, qsq, c0.x, c0.y, c0.z, c0.w);
            float d1 = dist_exact(qx, qy, qz, qsq, c1.x, c1.y, c1.z, c1.w);
            float d2 = dist_exact(qx, qy, qz, qsq, c2.x, c2.y, c2.z, c2.w);
            float d3 = dist_exact(qx, qy, qz, qsq, c3.x, c3.y, c3.z, c3.w);
            if (d0 < bd[15]) insert16(d0, gbase + j + 0, bd, bi);
            if (d1 < bd[15]) insert16(d1, gbase + j + 1, bd, bi);
            if (d2 < bd[15]) insert16(d2, gbase + j + 2, bd, bi);
            if (d3 < bd[15]) insert16(d3, gbase + j + 3, bd, bi);
        }
        __syncthreads();
    }
#pragma unroll
    for (int s = 0; s < 16; ++s) g_nbr[q * KNN + s] = bi[s];
}

// ---------------- K2: xw = x @ fW1[0:32,:] + fb1 ; zero g_agg ----------------
// grid = 256 blocks of 128 nodes, 256 thr.
__global__ void __launch_bounds__(256) xw_kernel(const float* __restrict__ x,
                                                 const float* __restrict__ fW1,
                                                 const float* __restrict__ fb1) {
    __shared__ float sX[32 * 128];   // [i][n]
    __shared__ float sW[32 * 64];    // [i][j]
    __shared__ float sB[64];
    int t = threadIdx.x, nb = blockIdx.x * 128;
    {
        int n = t & 127, ih = (t >> 7) * 16;
        const float4* xr = (const float4*)(x + (size_t)(nb + n) * DIN + ih);
#pragma unroll
        for (int c4 = 0; c4 < 4; ++c4) {
            float4 v = xr[c4]; int i = ih + c4 * 4;
            sX[(i + 0) * 128 + n] = v.x; sX[(i + 1) * 128 + n] = v.y;
            sX[(i + 2) * 128 + n] = v.z; sX[(i + 3) * 128 + n] = v.w;
        }
    }
    for (int idx = t * 4; idx < 2048; idx += 1024)
        *(float4*)&sW[idx] = *(const float4*)&fW1[idx];
    if (t < 64) sB[t] = fb1[t];
    __syncthreads();

    int n0 = (t & 31) * 4, j0 = (t >> 5) * 8;
    float acc[4][8];
#pragma unroll
    for (int r = 0; r < 4; ++r)
#pragma unroll
        for (int c = 0; c < 8; ++c) acc[r][c] = 0.f;
#pragma unroll
    for (int i = 0; i < 32; ++i) {
        float4 a  = *(float4*)&sX[i * 128 + n0];
        float4 b0 = *(float4*)&sW[i * 64 + j0];
        float4 b1 = *(float4*)&sW[i * 64 + j0 + 4];
        float av[4] = {a.x, a.y, a.z, a.w};
        float bv[8] = {b0.x, b0.y, b0.z, b0.w, b1.x, b1.y, b1.z, b1.w};
#pragma unroll
        for (int r = 0; r < 4; ++r)
#pragma unroll
            for (int c = 0; c < 8; ++c) acc[r][c] = fmaf(av[r], bv[c], acc[r][c]);
    }
#pragma unroll
    for (int r = 0; r < 4; ++r) {
        int n = nb + n0 + r;
        float4 o0 = make_float4(acc[r][0] + sB[j0], acc[r][1] + sB[j0 + 1],
                                acc[r][2] + sB[j0 + 2], acc[r][3] + sB[j0 + 3]);
        float4 o1 = make_float4(acc[r][4] + sB[j0 + 4], acc[r][5] + sB[j0 + 5],
                                acc[r][6] + sB[j0 + 6], acc[r][7] + sB[j0 + 7]);
        *(float4*)&g_xw[(size_t)n * DH + j0]     = o0;
        *(float4*)&g_xw[(size_t)n * DH + j0 + 4] = o1;
        float4 z4 = make_float4(0.f, 0.f, 0.f, 0.f);
        *(float4*)&g_agg[(size_t)n * DH + j0]     = z4;
        *(float4*)&g_agg[(size_t)n * DH + j0 + 4] = z4;
    }
}

// ---------------- K3: edge MLP + atomic segment max ----------------
// block = 4 queries = 64 edges, 128 thr, grid = 8192.
__global__ void __launch_bounds__(128) edge_kernel(const float* __restrict__ pos,
                                                   const float* __restrict__ fW1,
                                                   const float* __restrict__ fW2,
                                                   const float* __restrict__ fb2) {
    __shared__ float sW2[64 * 64];   // [i][j]
    __shared__ float sH [64 * 64];   // [i][e]
    __shared__ float sXW[4 * 64];
    __shared__ float sWp[3 * 64];
    __shared__ float sB2[64];
    __shared__ int   sNbr[64];
    __shared__ float sPq[12];

    int t = threadIdx.x, q0 = blockIdx.x * 4;
    for (int idx = t * 4; idx < 4096; idx += 512)
        *(float4*)&sW2[idx] = *(const float4*)&fW2[idx];
    for (int idx = t; idx < 256; idx += 128)
        sXW[idx] = g_xw[(size_t)q0 * DH + idx];
    for (int idx = t; idx < 192; idx += 128)          // FIX: was `if (t < 192)` with 128 threads
        sWp[idx] = fW1[32 * 64 + idx];                //      -> dz row was uninitialized
    if (t < 64)  { sB2[t] = fb2[t]; sNbr[t] = g_nbr[q0 * KNN + t]; }
    if (t < 12)  sPq[t] = pos[q0 * 3 + t];
    __syncthreads();

    // phase 1: sH[i][e] = relu(xw[q][i] + dpos . Wp[:,i])
    {
        int e = t & 63, i0 = (t >> 6) * 32, ql = e >> 4;
        int nbr = sNbr[e];
        float dx = sPq[ql * 3 + 0] - pos[nbr * 3 + 0];
        float dy = sPq[ql * 3 + 1] - pos[nbr * 3 + 1];
        float dz = sPq[ql * 3 + 2] - pos[nbr * 3 + 2];
#pragma unroll
        for (int ib = 0; ib < 32; ib += 4) {
            int i = i0 + ib;
            float4 xw = *(float4*)&sXW[ql * 64 + i];
            float4 w0 = *(float4*)&sWp[0 * 64 + i];
            float4 w1 = *(float4*)&sWp[1 * 64 + i];
            float4 w2 = *(float4*)&sWp[2 * 64 + i];
            sH[(i + 0) * 64 + e] = fmaxf(fmaf(dz, w2.x, fmaf(dy, w1.x, fmaf(dx, w0.x, xw.x))), 0.f);
            sH[(i + 1) * 64 + e] = fmaxf(fmaf(dz, w2.y, fmaf(dy, w1.y, fmaf(dx, w0.y, xw.y))), 0.f);
            sH[(i + 2) * 64 + e] = fmaxf(fmaf(dz, w2.z, fmaf(dy, w1.z, fmaf(dx, w0.z, xw.z))), 0.f);
            sH[(i + 3) * 64 + e] = fmaxf(fmaf(dz, w2.w, fmaf(dy, w1.w, fmaf(dx, w0.w, xw.w))), 0.f);
        }
    }
    __syncthreads();

    // phase 2: h2 = relu(h1 @ W2 + b2), atomicMax into g_agg[nbr]
    int e0 = (t & 15) * 4, j0 = (t >> 4) * 8;
    float acc[4][8];
#pragma unroll
    for (int r = 0; r < 4; ++r)
#pragma unroll
        for (int c = 0; c < 8; ++c) acc[r][c] = 0.f;
#pragma unroll
    for (int i = 0; i < 64; ++i) {
        float4 a  = *(float4*)&sH[i * 64 + e0];
        float4 b0 = *(float4*)&sW2[i * 64 + j0];
        float4 b1 = *(float4*)&sW2[i * 64 + j0 + 4];
        float av[4] = {a.x, a.y, a.z, a.w};
        float bv[8] = {b0.x, b0.y, b0.z, b0.w, b1.x, b1.y, b1.z, b1.w};
#pragma unroll
        for (int r = 0; r < 4; ++r)
#pragma unroll
            for (int c = 0; c < 8; ++c) acc[r][c] = fmaf(av[r], bv[c], acc[r][c]);
    }
#pragma unroll
    for (int r = 0; r < 4; ++r) {
        int nbr = sNbr[e0 + r];
        int* dst = (int*)&g_agg[(size_t)nbr * DH + j0];
#pragma unroll
        for (int c = 0; c < 8; ++c) {
            float v = fmaxf(acc[r][c] + sB2[j0 + c], 0.f);
            if (v > 0.f) atomicMax(&dst[c], __float_as_int(v));
        }
    }
}

// ---------------- K4: out = relu(agg @ gW + gb) ----------------
// block = 64 nodes, 256 thr, grid = 512.
__global__ void __launch_bounds__(256) out_kernel(const float* __restrict__ gW,
                                                  const float* __restrict__ gb,
                                                  float* __restrict__ out) {
    __shared__ float sA[64 * 64];    // [i][n]
    __shared__ float sW[64 * 128];   // [i][j]
    __shared__ float sB[128];
    int t = threadIdx.x, nb = blockIdx.x * 64;
    {
        int n = t & 63, ih = (t >> 6) * 16;
        const float4* ar = (const float4*)(g_agg + (size_t)(nb + n) * DH + ih);
#pragma unroll
        for (int c4 = 0; c4 < 4; ++c4) {
            float4 v = ar[c4]; int i = ih + c4 * 4;
            sA[(i + 0) * 64 + n] = v.x; sA[(i + 1) * 64 + n] = v.y;
            sA[(i + 2) * 64 + n] = v.z; sA[(i + 3) * 64 + n] = v.w;
        }
    }
    for (int idx = t * 4; idx < 8192; idx += 1024)
        *(float4*)&sW[idx] = *(const float4*)&gW[idx];
    if (t < 128) sB[t] = gb[t];
    __syncthreads();

    int n0 = (t & 15) * 4, j0 = (t >> 4) * 8;
    float acc[4][8];
#pragma unroll
    for (int r = 0; r < 4; ++r)
#pragma unroll
        for (int c = 0; c < 8; ++c) acc[r][c] = 0.f;
#pragma unroll
    for (int i = 0; i < 64; ++i) {
        float4 a  = *(float4*)&sA[i * 64 + n0];
        float4 b0 = *(float4*)&sW[i * 128 + j0];
        float4 b1 = *(float4*)&sW[i * 128 + j0 + 4];
        float av[4] = {a.x, a.y, a.z, a.w};
        float bv[8] = {b0.x, b0.y, b0.z, b0.w, b1.x, b1.y, b1.z, b1.w};
#pragma unroll
        for (int r = 0; r < 4; ++r)
#pragma unroll
            for (int c = 0; c < 8; ++c) acc[r][c] = fmaf(av[r], bv[c], acc[r][c]);
    }
#pragma unroll
    for (int r = 0; r < 4; ++r) {
        int n = nb + n0 + r;
        float4 o0 = make_float4(fmaxf(acc[r][0] + sB[j0], 0.f),     fmaxf(acc[r][1] + sB[j0 + 1], 0.f),
                                fmaxf(acc[r][2] + sB[j0 + 2], 0.f), fmaxf(acc[r][3] + sB[j0 + 3], 0.f));
        float4 o1 = make_float4(fmaxf(acc[r][4] + sB[j0 + 4], 0.f), fmaxf(acc[r][5] + sB[j0 + 5], 0.f),
                                fmaxf(acc[r][6] + sB[j0 + 6], 0.f), fmaxf(acc[r][7] + sB[j0 + 7], 0.f));
        *(float4*)&out[(size_t)n * DOUT + j0]     = o0;
        *(float4*)&out[(size_t)n * DOUT + j0 + 4] = o1;
    }
}

// ---------------- K5: append pos (+ batch as float) if tuple flattened ----------------
__global__ void __launch_bounds__(256) tail_kernel(const float* __restrict__ pos,
                                                   float* __restrict__ out,
                                                   int out_size) {
    int idx = blockIdx.x * blockDim.x + threadIdx.x;
    const int base = NTOT * DOUT;
    int pos_n = NTOT * 3;
    if (out_size >= base + pos_n && idx < pos_n)
        out[base + idx] = pos[idx];
    if (out_size >= base + pos_n + NTOT && idx < NTOT)
        out[base + pos_n + idx] = (float)(idx / NPER);
}

extern "C" void kernel_launch(void* const* d_in, const int* in_sizes, int n_in,
                              void* d_out, int out_size) {
    const float* x    = (const float*)d_in[0];
    const float* pos  = (const float*)d_in[1];
    // d_in[2] = batch (int32): deterministic repeat(arange(B), NPER)
    const float* fW1  = (const float*)d_in[3];
    const float* fb1  = (const float*)d_in[4];
    const float* fW2  = (const float*)d_in[5];
    const float* fb2  = (const float*)d_in[6];
    const float* gW   = (const float*)d_in[7];
    const float* gb   = (const float*)d_in[8];
    float* out = (float*)d_out;

    knn_kernel<<<128, 256>>>(pos);
    xw_kernel<<<256, 256>>>(x, fW1, fb1);
    edge_kernel<<<8192, 128>>>(pos, fW1, fW2, fb2);
    out_kernel<<<512, 256>>>(gW, gb, out);
    if (out_size > NTOT * DOUT)
        tail_kernel<<<512, 256>>>(pos, out, out_size);
}

// round 8
// speedup vs baseline: 1.0531x; 1.0531x over previous
#include <cuda_runtime.h>
#include <cstdint>

#define NB      8
#define NPER    4096
#define NTOT    32768
#define KNN     16
#define DIN     32
#define DH      64
#define DOUT    128

// ---------------- device scratch ----------------
static __device__ int   g_nbr[NTOT * KNN];
static __device__ float g_xw [NTOT * DH];
static __device__ float g_agg[NTOT * DH];

// ---------------- exact-arithmetic helpers (match XLA fp32) ----------------
__device__ __forceinline__ float sq3_exact(float x, float y, float z) {
    return __fadd_rn(__fadd_rn(__fmul_rn(x, x), __fmul_rn(y, y)), __fmul_rn(z, z));
}
__device__ __forceinline__ float dist_exact(float qx, float qy, float qz, float qsq,
                                            float cx, float cy, float cz, float csq) {
    float dot = __fmaf_rn(qz, cz, __fmaf_rn(qy, cy, __fmul_rn(qx, cx)));
    return __fsub_rn(__fadd_rn(qsq, csq), __fmul_rn(2.0f, dot));
}

// float bits -> order-preserving unsigned
__device__ __forceinline__ unsigned int ordbits(unsigned int b) {
    return (b & 0x80000000u) ? ~b : (b | 0x80000000u);
}

// sorted-ascending insert of packed (dist,idx) key into 16-deep register list
__device__ __forceinline__ void insk16(unsigned long long k, unsigned long long (&K)[16]) {
#pragma unroll
    for (int s = 0; s < 16; ++s) {
        bool p = k < K[s];
        unsigned long long lo = p ? k : K[s];
        unsigned long long hi = p ? K[s] : k;
        K[s] = lo; k = hi;
    }
}

// ---------------- K1: per-graph brute-force KNN, buffered selection ----------------
// grid = 128 (16 blocks/graph), 256 thr; thread = one query; warp shares candidate
// stream (broadcast LDS). Passing candidates go to a per-lane smem buffer via
// PREDICATED append (no warp divergence); drains are warp-synchronized.
#define KBUF 15
__global__ void __launch_bounds__(256) knn_kernel(const float* __restrict__ pos) {
    __shared__ float4 sc[1024];                 // staged candidates (x,y,z,sq)
    __shared__ uint2  sbuf[256 * KBUF];         // per-lane append buffers (dbits, lidx)

    int graph = blockIdx.x >> 4;
    int q     = graph * NPER + (blockIdx.x & 15) * 256 + threadIdx.x;
    int cbase = graph * NPER;

    float qx = pos[q * 3 + 0], qy = pos[q * 3 + 1], qz = pos[q * 3 + 2];
    float qsq = sq3_exact(qx, qy, qz);

    unsigned long long K[16];
#pragma unroll
    for (int s = 0; s < 16; ++s) K[s] = ~0ull;
    float worstd = __int_as_float(0x7f800000);   // +inf
    int cnt = 0;
    uint2* mybuf = &sbuf[threadIdx.x * KBUF];

#pragma unroll 1
    for (int chunk = 0; chunk < 4; ++chunk) {
        // stage 1024 candidates
#pragma unroll
        for (int u = 0; u < 4; ++u) {
            int li = threadIdx.x + u * 256;
            int gi = cbase + chunk * 1024 + li;
            float x = pos[gi * 3 + 0], y = pos[gi * 3 + 1], z = pos[gi * 3 + 2];
            sc[li] = make_float4(x, y, z, sq3_exact(x, y, z));
        }
        __syncthreads();

#pragma unroll 1
        for (int j = 0; j < 1024; j += 4) {
#pragma unroll
            for (int u = 0; u < 4; ++u) {
                float4 c = sc[j + u];
                float d = dist_exact(qx, qy, qz, qsq, c.x, c.y, c.z, c.w);
                // append iff d <= worstd; NaN worstd (list not full) -> append all.
                if (!(d > worstd)) {
                    mybuf[cnt] = make_uint2(__float_as_uint(d),
                                            (unsigned)(chunk * 1024 + j + u));
                    cnt++;
                }
            }
            if (__any_sync(0xffffffffu, cnt >= KBUF - 3)) {
                // warp-synchronized drain
                for (int k = 0; k < cnt; ++k) {
                    uint2 e = mybuf[k];
                    unsigned long long key =
                        ((unsigned long long)ordbits(e.x) << 16) | e.y;
                    if (key < K[15]) insk16(key, K);
                }
                cnt = 0;
                unsigned int o = (unsigned int)(K[15] >> 16);
                unsigned int b = (o & 0x80000000u) ? (o & 0x7FFFFFFFu) : ~o;
                worstd = __uint_as_float(b);     // NaN while list not full (safe)
            }
        }
        __syncthreads();
    }

    // final drain
    for (int k = 0; k < cnt; ++k) {
        uint2 e = mybuf[k];
        unsigned long long key = ((unsigned long long)ordbits(e.x) << 16) | e.y;
        if (key < K[15]) insk16(key, K);
    }

#pragma unroll
    for (int s = 0; s < 16; ++s)
        g_nbr[q * KNN + s] = cbase + (int)(K[s] & 0xFFFFull);
}

// ---------------- K2: xw = x @ fW1[0:32,:] + fb1 ; zero g_agg ----------------
// grid = 256 blocks of 128 nodes, 256 thr.
__global__ void __launch_bounds__(256) xw_kernel(const float* __restrict__ x,
                                                 const float* __restrict__ fW1,
                                                 const float* __restrict__ fb1) {
    __shared__ float sX[32 * 128];   // [i][n]
    __shared__ float sW[32 * 64];    // [i][j]
    __shared__ float sB[64];
    int t = threadIdx.x, nb = blockIdx.x * 128;
    {
        int n = t & 127, ih = (t >> 7) * 16;
        const float4* xr = (const float4*)(x + (size_t)(nb + n) * DIN + ih);
#pragma unroll
        for (int c4 = 0; c4 < 4; ++c4) {
            float4 v = xr[c4]; int i = ih + c4 * 4;
            sX[(i + 0) * 128 + n] = v.x; sX[(i + 1) * 128 + n] = v.y;
            sX[(i + 2) * 128 + n] = v.z; sX[(i + 3) * 128 + n] = v.w;
        }
    }
    for (int idx = t * 4; idx < 2048; idx += 1024)
        *(float4*)&sW[idx] = *(const float4*)&fW1[idx];
    if (t < 64) sB[t] = fb1[t];
    __syncthreads();

    int n0 = (t & 31) * 4, j0 = (t >> 5) * 8;
    float acc[4][8];
#pragma unroll
    for (int r = 0; r < 4; ++r)
#pragma unroll
        for (int c = 0; c < 8; ++c) acc[r][c] = 0.f;
#pragma unroll
    for (int i = 0; i < 32; ++i) {
        float4 a  = *(float4*)&sX[i * 128 + n0];
        float4 b0 = *(float4*)&sW[i * 64 + j0];
        float4 b1 = *(float4*)&sW[i * 64 + j0 + 4];
        float av[4] = {a.x, a.y, a.z, a.w};
        float bv[8] = {b0.x, b0.y, b0.z, b0.w, b1.x, b1.y, b1.z, b1.w};
#pragma unroll
        for (int r = 0; r < 4; ++r)
#pragma unroll
            for (int c = 0; c < 8; ++c) acc[r][c] = fmaf(av[r], bv[c], acc[r][c]);
    }
#pragma unroll
    for (int r = 0; r < 4; ++r) {
        int n = nb + n0 + r;
        float4 o0 = make_float4(acc[r][0] + sB[j0], acc[r][1] + sB[j0 + 1],
                                acc[r][2] + sB[j0 + 2], acc[r][3] + sB[j0 + 3]);
        float4 o1 = make_float4(acc[r][4] + sB[j0 + 4], acc[r][5] + sB[j0 + 5],
                                acc[r][6] + sB[j0 + 6], acc[r][7] + sB[j0 + 7]);
        *(float4*)&g_xw[(size_t)n * DH + j0]     = o0;
        *(float4*)&g_xw[(size_t)n * DH + j0 + 4] = o1;
        float4 z4 = make_float4(0.f, 0.f, 0.f, 0.f);
        *(float4*)&g_agg[(size_t)n * DH + j0]     = z4;
        *(float4*)&g_agg[(size_t)n * DH + j0 + 4] = z4;
    }
}

// ---------------- K3: edge MLP + atomic segment max ----------------
// block = 4 queries = 64 edges, 128 thr, grid = 8192.
__global__ void __launch_bounds__(128) edge_kernel(const float* __restrict__ pos,
                                                   const float* __restrict__ fW1,
                                                   const float* __restrict__ fW2,
                                                   const float* __restrict__ fb2) {
    __shared__ float sW2[64 * 64];   // [i][j]
    __shared__ float sH [64 * 64];   // [i][e]
    __shared__ float sXW[4 * 64];
    __shared__ float sWp[3 * 64];
    __shared__ float sB2[64];
    __shared__ int   sNbr[64];
    __shared__ float sPq[12];

    int t = threadIdx.x, q0 = blockIdx.x * 4;
    for (int idx = t * 4; idx < 4096; idx += 512)
        *(float4*)&sW2[idx] = *(const float4*)&fW2[idx];
    for (int idx = t; idx < 256; idx += 128)
        sXW[idx] = g_xw[(size_t)q0 * DH + idx];
    for (int idx = t; idx < 192; idx += 128)
        sWp[idx] = fW1[32 * 64 + idx];               // rows 32..34 (pos part)
    if (t < 64)  { sB2[t] = fb2[t]; sNbr[t] = g_nbr[q0 * KNN + t]; }
    if (t < 12)  sPq[t] = pos[q0 * 3 + t];
    __syncthreads();

    // phase 1: sH[i][e] = relu(xw[q][i] + dpos . Wp[:,i])
    {
        int e = t & 63, i0 = (t >> 6) * 32, ql = e >> 4;
        int nbr = sNbr[e];
        float dx = sPq[ql * 3 + 0] - pos[nbr * 3 + 0];
        float dy = sPq[ql * 3 + 1] - pos[nbr * 3 + 1];
        float dz = sPq[ql * 3 + 2] - pos[nbr * 3 + 2];
#pragma unroll
        for (int ib = 0; ib < 32; ib += 4) {
            int i = i0 + ib;
            float4 xw = *(float4*)&sXW[ql * 64 + i];
            float4 w0 = *(float4*)&sWp[0 * 64 + i];
            float4 w1 = *(float4*)&sWp[1 * 64 + i];
            float4 w2 = *(float4*)&sWp[2 * 64 + i];
            sH[(i + 0) * 64 + e] = fmaxf(fmaf(dz, w2.x, fmaf(dy, w1.x, fmaf(dx, w0.x, xw.x))), 0.f);
            sH[(i + 1) * 64 + e] = fmaxf(fmaf(dz, w2.y, fmaf(dy, w1.y, fmaf(dx, w0.y, xw.y))), 0.f);
            sH[(i + 2) * 64 + e] = fmaxf(fmaf(dz, w2.z, fmaf(dy, w1.z, fmaf(dx, w0.z, xw.z))), 0.f);
            sH[(i + 3) * 64 + e] = fmaxf(fmaf(dz, w2.w, fmaf(dy, w1.w, fmaf(dx, w0.w, xw.w))), 0.f);
        }
    }
    __syncthreads();

    // phase 2: h2 = relu(h1 @ W2 + b2), atomicMax into g_agg[nbr]
    int e0 = (t & 15) * 4, j0 = (t >> 4) * 8;
    float acc[4][8];
#pragma unroll
    for (int r = 0; r < 4; ++r)
#pragma unroll
        for (int c = 0; c < 8; ++c) acc[r][c] = 0.f;
#pragma unroll
    for (int i = 0; i < 64; ++i) {
        float4 a  = *(float4*)&sH[i * 64 + e0];
        float4 b0 = *(float4*)&sW2[i * 64 + j0];
        float4 b1 = *(float4*)&sW2[i * 64 + j0 + 4];
        float av[4] = {a.x, a.y, a.z, a.w};
        float bv[8] = {b0.x, b0.y, b0.z, b0.w, b1.x, b1.y, b1.z, b1.w};
#pragma unroll
        for (int r = 0; r < 4; ++r)
#pragma unroll
            for (int c = 0; c < 8; ++c) acc[r][c] = fmaf(av[r], bv[c], acc[r][c]);
    }
#pragma unroll
    for (int r = 0; r < 4; ++r) {
        int nbr = sNbr[e0 + r];
        int* dst = (int*)&g_agg[(size_t)nbr * DH + j0];
#pragma unroll
        for (int c = 0; c < 8; ++c) {
            float v = fmaxf(acc[r][c] + sB2[j0 + c], 0.f);
            if (v > 0.f) atomicMax(&dst[c], __float_as_int(v));
        }
    }
}

// ---------------- K4: out = relu(agg @ gW + gb) ----------------
// block = 64 nodes, 256 thr, grid = 512.
__global__ void __launch_bounds__(256) out_kernel(const float* __restrict__ gW,
                                                  const float* __restrict__ gb,
                                                  float* __restrict__ out) {
    __shared__ float sA[64 * 64];    // [i][n]
    __shared__ float sW[64 * 128];   // [i][j]
    __shared__ float sB[128];
    int t = threadIdx.x, nb = blockIdx.x * 64;
    {
        int n = t & 63, ih = (t >> 6) * 16;
        const float4* ar = (const float4*)(g_agg + (size_t)(nb + n) * DH + ih);
#pragma unroll
        for (int c4 = 0; c4 < 4; ++c4) {
            float4 v = ar[c4]; int i = ih + c4 * 4;
            sA[(i + 0) * 64 + n] = v.x; sA[(i + 1) * 64 + n] = v.y;
            sA[(i + 2) * 64 + n] = v.z; sA[(i + 3) * 64 + n] = v.w;
        }
    }
    for (int idx = t * 4; idx < 8192; idx += 1024)
        *(float4*)&sW[idx] = *(const float4*)&gW[idx];
    if (t < 128) sB[t] = gb[t];
    __syncthreads();

    int n0 = (t & 15) * 4, j0 = (t >> 4) * 8;
    float acc[4][8];
#pragma unroll
    for (int r = 0; r < 4; ++r)
#pragma unroll
        for (int c = 0; c < 8; ++c) acc[r][c] = 0.f;
#pragma unroll
    for (int i = 0; i < 64; ++i) {
        float4 a  = *(float4*)&sA[i * 64 + n0];
        float4 b0 = *(float4*)&sW[i * 128 + j0];
        float4 b1 = *(float4*)&sW[i * 128 + j0 + 4];
        float av[4] = {a.x, a.y, a.z, a.w};
        float bv[8] = {b0.x, b0.y, b0.z, b0.w, b1.x, b1.y, b1.z, b1.w};
#pragma unroll
        for (int r = 0; r < 4; ++r)
#pragma unroll
            for (int c = 0; c < 8; ++c) acc[r][c] = fmaf(av[r], bv[c], acc[r][c]);
    }
#pragma unroll
    for (int r = 0; r < 4; ++r) {
        int n = nb + n0 + r;
        float4 o0 = make_float4(fmaxf(acc[r][0] + sB[j0], 0.f),     fmaxf(acc[r][1] + sB[j0 + 1], 0.f),
                                fmaxf(acc[r][2] + sB[j0 + 2], 0.f), fmaxf(acc[r][3] + sB[j0 + 3], 0.f));
        float4 o1 = make_float4(fmaxf(acc[r][4] + sB[j0 + 4], 0.f), fmaxf(acc[r][5] + sB[j0 + 5], 0.f),
                                fmaxf(acc[r][6] + sB[j0 + 6], 0.f), fmaxf(acc[r][7] + sB[j0 + 7], 0.f));
        *(float4*)&out[(size_t)n * DOUT + j0]     = o0;
        *(float4*)&out[(size_t)n * DOUT + j0 + 4] = o1;
    }
}

// ---------------- K5: append pos (+ batch as float) if tuple flattened ----------------
__global__ void __launch_bounds__(256) tail_kernel(const float* __restrict__ pos,
                                                   float* __restrict__ out,
                                                   int out_size) {
    int idx = blockIdx.x * blockDim.x + threadIdx.x;
    const int base = NTOT * DOUT;
    int pos_n = NTOT * 3;
    if (out_size >= base + pos_n && idx < pos_n)
        out[base + idx] = pos[idx];
    if (out_size >= base + pos_n + NTOT && idx < NTOT)
        out[base + pos_n + idx] = (float)(idx / NPER);
}

extern "C" void kernel_launch(void* const* d_in, const int* in_sizes, int n_in,
                              void* d_out, int out_size) {
    const float* x    = (const float*)d_in[0];
    const float* pos  = (const float*)d_in[1];
    // d_in[2] = batch (int32): deterministic repeat(arange(B), NPER)
    const float* fW1  = (const float*)d_in[3];
    const float* fb1  = (const float*)d_in[4];
    const float* fW2  = (const float*)d_in[5];
    const float* fb2  = (const float*)d_in[6];
    const float* gW   = (const float*)d_in[7];
    const float* gb   = (const float*)d_in[8];
    float* out = (float*)d_out;

    knn_kernel<<<128, 256>>>(pos);
    xw_kernel<<<256, 256>>>(x, fW1, fb1);
    edge_kernel<<<8192, 128>>>(pos, fW1, fW2, fb2);
    out_kernel<<<512, 256>>>(gW, gb, out);
    if (out_size > NTOT * DOUT)
        tail_kernel<<<512, 256>>>(pos, out, out_size);
}